// round 11
// baseline (speedup 1.0000x reference)
#include <cuda_runtime.h>

#define BSZ 2
#define TLEN 2048
#define NH 16
#define PP 64
#define NN 64
#define CHL 64                 // chunk length
#define NCH (TLEN / CHL)       // 32 chunks
#define LDS_ (NN + 4)          // padded row stride (68)
#define IDX(r,c) ((r) * LDS_ + (c))

// Scratch (device globals; allocation-free).
__device__ float g_S [BSZ * NH * NCH * PP * NN];  // per-chunk local final state [bh][c][p][n]
__device__ float g_H0[BSZ * NH * NCH * PP * NN];  // state entering each chunk   [bh][c][p][n]
__device__ float g_A [BSZ * NH * NCH];            // per-chunk total decay
__device__ float g_a [BSZ * NH * NCH * CHL];      // a_t = exp(negA*cum_t)

// ---------------------------------------------------------------------------
// KA: fused intra-chunk kernel. One block per (b,h,c), 256 threads.
//   GEMM1: G[t,s]   = sum_n C[t,n] B[s,n]          (strided 4x4 tile)
//   W^T   : sWT[s,t] = (s<=t) ? exp(negA*(cum_t-cum_s))*delta_s*G : 0
//   GEMM-S: S[p,n]  = sum_s r_s B[s,n] X[s,p]      (consecutive tile, float4)
//   GEMM2: y[t,p]   = sum_{s<=t} W[t,s] X[s,p]     (consecutive tile, triangular)
// ---------------------------------------------------------------------------
__global__ __launch_bounds__(256) void kA_intra(
    const float* __restrict__ X,      // [B,T,H,P]
    const float* __restrict__ delta,  // [B,T,H]
    const float* __restrict__ Bm,     // [B,T,N]
    const float* __restrict__ Cm,     // [B,T,N]
    const float* __restrict__ A_log,  // [H]
    float* __restrict__ y)            // [B,T,H,P]
{
    extern __shared__ float smem[];
    float* sB = smem;                 // [CHL][LDS_] raw B, later scaled by r_s
    float* sC = sB + CHL * LDS_;
    float* sX = sC + CHL * LDS_;
    float* sW = sX + CHL * LDS_;      // W transposed: sW[s][t]

    __shared__ float sh_d[CHL], sh_cum[CHL], sh_r[CHL];
    __shared__ float sh_wsum[2];

    const int blk = blockIdx.x;            // (b*NH+h)*NCH + c
    const int c  = blk % NCH;
    const int hh = (blk / NCH) % NH;
    const int b  = blk / (NCH * NH);
    const int t0 = c * CHL;
    const int tid = threadIdx.x;
    const int lane = tid & 31;

    const float negA = -__expf(A_log[hh]);

    // ---- stage delta + warp-level inclusive scan (phase 1) ----
    if (tid < CHL) {
        const float d = __ldg(delta + ((size_t)b * TLEN + t0 + tid) * NH + hh);
        sh_d[tid] = d;
        float v = d;
        #pragma unroll
        for (int off = 1; off < 32; off <<= 1) {
            const float t = __shfl_up_sync(0xffffffffu, v, off);
            if (lane >= off) v += t;
        }
        sh_cum[tid] = v;
        if (lane == 31) sh_wsum[tid >> 5] = v;
    }

    // ---- stage B, C, X ----
    for (int i = tid; i < CHL * NN / 4; i += 256) {
        const int r = i >> 4, q = i & 15;
        *(float4*)&sB[IDX(r, q * 4)] =
            __ldg((const float4*)(Bm + ((size_t)b * TLEN + t0 + r) * NN) + q);
        *(float4*)&sC[IDX(r, q * 4)] =
            __ldg((const float4*)(Cm + ((size_t)b * TLEN + t0 + r) * NN) + q);
    }
    for (int i = tid; i < CHL * PP / 4; i += 256) {
        const int r = i >> 4, q = i & 15;
        *(float4*)&sX[IDX(r, q * 4)] =
            __ldg((const float4*)(X + (((size_t)b * TLEN + t0 + r) * NH + hh) * PP) + q);
    }
    __syncthreads();   // sync1: staging + scan phase1 done

    // ---- scan phase 2: cross-warp fixup, r_s, a_t, A_c ----
    if (tid < CHL) {
        const float cum = sh_cum[tid] + (tid >= 32 ? sh_wsum[0] : 0.f);
        sh_cum[tid] = cum;
        const float cumTot = sh_wsum[0] + sh_wsum[1];
        g_a[(size_t)blk * CHL + tid] = __expf(negA * cum);
        sh_r[tid] = __expf(negA * (cumTot - cum)) * sh_d[tid];
        if (tid == 0) g_A[blk] = __expf(negA * cumTot);
    }

    const int i = tid & 15;
    const int j = tid >> 4;

    // ---- GEMM1: G[t,s], t = j+16tj, s = i+16si, reduce over n ----
    float g[4][4];
    #pragma unroll
    for (int a0 = 0; a0 < 4; ++a0)
        #pragma unroll
        for (int a1 = 0; a1 < 4; ++a1) g[a0][a1] = 0.f;

    #pragma unroll 4
    for (int n4 = 0; n4 < NN / 4; ++n4) {
        float4 cv[4], bv[4];
        #pragma unroll
        for (int tj = 0; tj < 4; ++tj) cv[tj] = *(const float4*)&sC[IDX(j + 16 * tj, n4 * 4)];
        #pragma unroll
        for (int si = 0; si < 4; ++si) bv[si] = *(const float4*)&sB[IDX(i + 16 * si, n4 * 4)];
        #pragma unroll
        for (int tj = 0; tj < 4; ++tj)
            #pragma unroll
            for (int si = 0; si < 4; ++si) {
                g[tj][si] = fmaf(cv[tj].x, bv[si].x, g[tj][si]);
                g[tj][si] = fmaf(cv[tj].y, bv[si].y, g[tj][si]);
                g[tj][si] = fmaf(cv[tj].z, bv[si].z, g[tj][si]);
                g[tj][si] = fmaf(cv[tj].w, bv[si].w, g[tj][si]);
            }
    }
    __syncthreads();   // sync2: GEMM1 reads of raw sB done; sh_cum finalized

    // ---- write W transposed ----
    #pragma unroll
    for (int tj = 0; tj < 4; ++tj) {
        const int t = j + 16 * tj;
        const float ct = sh_cum[t];
        #pragma unroll
        for (int si = 0; si < 4; ++si) {
            const int s = i + 16 * si;
            const float arg = negA * (ct - sh_cum[s]);
            const float e = __expf(fminf(arg, 0.f));
            sW[IDX(s, t)] = (s <= t) ? e * sh_d[s] * g[tj][si] : 0.f;
        }
    }
    // ---- scale sB in place by r_s ----
    for (int idx = tid; idx < CHL * NN / 4; idx += 256) {
        const int r = idx >> 4, q = idx & 15;
        float4 v = *(float4*)&sB[IDX(r, q * 4)];
        const float rr = sh_r[r];
        v.x *= rr; v.y *= rr; v.z *= rr; v.w *= rr;
        *(float4*)&sB[IDX(r, q * 4)] = v;
    }
    __syncthreads();   // sync3: sW and scaled sB visible

    // ---- GEMM-S: S[p][n] = sum_s sB'[s,n] sX[s,p]; n=4i.., p=4j.. ----
    {
        float acc[4][4];   // [pj][ni]
        #pragma unroll
        for (int a0 = 0; a0 < 4; ++a0)
            #pragma unroll
            for (int a1 = 0; a1 < 4; ++a1) acc[a0][a1] = 0.f;

        #pragma unroll 8
        for (int s = 0; s < CHL; ++s) {
            const float4 bv = *(const float4*)&sB[IDX(s, 4 * i)];
            const float4 xv = *(const float4*)&sX[IDX(s, 4 * j)];
            acc[0][0] = fmaf(xv.x, bv.x, acc[0][0]);
            acc[0][1] = fmaf(xv.x, bv.y, acc[0][1]);
            acc[0][2] = fmaf(xv.x, bv.z, acc[0][2]);
            acc[0][3] = fmaf(xv.x, bv.w, acc[0][3]);
            acc[1][0] = fmaf(xv.y, bv.x, acc[1][0]);
            acc[1][1] = fmaf(xv.y, bv.y, acc[1][1]);
            acc[1][2] = fmaf(xv.y, bv.z, acc[1][2]);
            acc[1][3] = fmaf(xv.y, bv.w, acc[1][3]);
            acc[2][0] = fmaf(xv.z, bv.x, acc[2][0]);
            acc[2][1] = fmaf(xv.z, bv.y, acc[2][1]);
            acc[2][2] = fmaf(xv.z, bv.z, acc[2][2]);
            acc[2][3] = fmaf(xv.z, bv.w, acc[2][3]);
            acc[3][0] = fmaf(xv.w, bv.x, acc[3][0]);
            acc[3][1] = fmaf(xv.w, bv.y, acc[3][1]);
            acc[3][2] = fmaf(xv.w, bv.z, acc[3][2]);
            acc[3][3] = fmaf(xv.w, bv.w, acc[3][3]);
        }
        float* Sp = g_S + (size_t)blk * PP * NN;
        #pragma unroll
        for (int pj = 0; pj < 4; ++pj)
            *(float4*)(Sp + (4 * j + pj) * NN + 4 * i) =
                make_float4(acc[pj][0], acc[pj][1], acc[pj][2], acc[pj][3]);
    }

    // ---- GEMM2: Y1[t,p] = sum_{s<=t} W[t,s] X[s,p]; t=4j.., p=4i.. ----
    {
        const int sBound = ((tid >> 5) + 1) * 8;   // warp-uniform triangular bound
        float acc[4][4];   // [tj][pi]
        #pragma unroll
        for (int a0 = 0; a0 < 4; ++a0)
            #pragma unroll
            for (int a1 = 0; a1 < 4; ++a1) acc[a0][a1] = 0.f;

        #pragma unroll 8
        for (int s = 0; s < sBound; ++s) {
            const float4 wv = *(const float4*)&sW[IDX(s, 4 * j)];
            const float4 xv = *(const float4*)&sX[IDX(s, 4 * i)];
            acc[0][0] = fmaf(wv.x, xv.x, acc[0][0]);
            acc[0][1] = fmaf(wv.x, xv.y, acc[0][1]);
            acc[0][2] = fmaf(wv.x, xv.z, acc[0][2]);
            acc[0][3] = fmaf(wv.x, xv.w, acc[0][3]);
            acc[1][0] = fmaf(wv.y, xv.x, acc[1][0]);
            acc[1][1] = fmaf(wv.y, xv.y, acc[1][1]);
            acc[1][2] = fmaf(wv.y, xv.z, acc[1][2]);
            acc[1][3] = fmaf(wv.y, xv.w, acc[1][3]);
            acc[2][0] = fmaf(wv.z, xv.x, acc[2][0]);
            acc[2][1] = fmaf(wv.z, xv.y, acc[2][1]);
            acc[2][2] = fmaf(wv.z, xv.z, acc[2][2]);
            acc[2][3] = fmaf(wv.z, xv.w, acc[2][3]);
            acc[3][0] = fmaf(wv.w, xv.x, acc[3][0]);
            acc[3][1] = fmaf(wv.w, xv.y, acc[3][1]);
            acc[3][2] = fmaf(wv.w, xv.z, acc[3][2]);
            acc[3][3] = fmaf(wv.w, xv.w, acc[3][3]);
        }
        #pragma unroll
        for (int tj = 0; tj < 4; ++tj) {
            const int t = 4 * j + tj;
            float* yrow = y + (((size_t)b * TLEN + t0 + t) * NH + hh) * PP;
            *(float4*)(yrow + 4 * i) =
                make_float4(acc[tj][0], acc[tj][1], acc[tj][2], acc[tj][3]);
        }
    }
}

// ---------------------------------------------------------------------------
// K2: cross-chunk scan, one thread per (bh, p, n). Fully unrolled over 32 chunks.
// ---------------------------------------------------------------------------
__global__ __launch_bounds__(256) void k2_scan(float* __restrict__ hlast) // [B,H,P,N]
{
    const int idx = blockIdx.x * 256 + threadIdx.x;   // bh*PP*NN + p*NN + n
    const int bh = idx >> 12;
    const int pn = idx & 4095;

    float h = 0.f;
    #pragma unroll
    for (int c = 0; c < NCH; ++c) {
        const size_t off = ((size_t)bh * NCH + c) * (PP * NN) + pn;
        g_H0[off] = h;
        h = fmaf(g_A[bh * NCH + c], h, g_S[off]);
    }
    hlast[(size_t)bh * PP * NN + pn] = h;
}

// ---------------------------------------------------------------------------
// KC: inter-chunk correction. One block per (b,h,c).
//   y[t,p] += a_t * sum_n C[t,n] H0[p,n]
// GEMM3 strided 4x4 tile; result staged via smem for float4 RMW of y.
// ---------------------------------------------------------------------------
__global__ __launch_bounds__(256) void kC_corr(
    const float* __restrict__ Cm,
    float* __restrict__ y)
{
    extern __shared__ float smem[];
    float* sC  = smem;                // [CHL][LDS_]
    float* sH  = sC + CHL * LDS_;     // [PP][LDS_]  -> later sY2[t][p]
    float* sY2 = sH;

    __shared__ float sh_a[CHL];

    const int blk = blockIdx.x;
    const int c  = blk % NCH;
    const int hh = (blk / NCH) % NH;
    const int b  = blk / (NCH * NH);
    const int t0 = c * CHL;
    const int tid = threadIdx.x;

    if (tid < CHL) sh_a[tid] = g_a[(size_t)blk * CHL + tid];
    for (int i = tid; i < CHL * NN / 4; i += 256) {
        const int r = i >> 4, q = i & 15;
        *(float4*)&sC[IDX(r, q * 4)] =
            __ldg((const float4*)(Cm + ((size_t)b * TLEN + t0 + r) * NN) + q);
    }
    {
        const float* Hp = g_H0 + (size_t)blk * PP * NN;
        for (int i = tid; i < PP * NN / 4; i += 256) {
            const int r = i >> 4, q = i & 15;
            *(float4*)&sH[IDX(r, q * 4)] = __ldg((const float4*)Hp + i);
        }
    }
    __syncthreads();

    const int i = tid & 15;
    const int j = tid >> 4;

    // GEMM3: Y2[t,p] = sum_n C[t,n] H0[p,n]; t = j+16tj, p = i+16pi
    float acc2[4][4];
    #pragma unroll
    for (int a0 = 0; a0 < 4; ++a0)
        #pragma unroll
        for (int a1 = 0; a1 < 4; ++a1) acc2[a0][a1] = 0.f;

    #pragma unroll 4
    for (int n4 = 0; n4 < NN / 4; ++n4) {
        float4 cv[4], hv[4];
        #pragma unroll
        for (int tj = 0; tj < 4; ++tj) cv[tj] = *(const float4*)&sC[IDX(j + 16 * tj, n4 * 4)];
        #pragma unroll
        for (int pi = 0; pi < 4; ++pi) hv[pi] = *(const float4*)&sH[IDX(i + 16 * pi, n4 * 4)];
        #pragma unroll
        for (int tj = 0; tj < 4; ++tj)
            #pragma unroll
            for (int pi = 0; pi < 4; ++pi) {
                acc2[tj][pi] = fmaf(cv[tj].x, hv[pi].x, acc2[tj][pi]);
                acc2[tj][pi] = fmaf(cv[tj].y, hv[pi].y, acc2[tj][pi]);
                acc2[tj][pi] = fmaf(cv[tj].z, hv[pi].z, acc2[tj][pi]);
                acc2[tj][pi] = fmaf(cv[tj].w, hv[pi].w, acc2[tj][pi]);
            }
    }
    __syncthreads();   // GEMM3 reads of sH done before sY2 overwrites it

    #pragma unroll
    for (int tj = 0; tj < 4; ++tj) {
        const int t = j + 16 * tj;
        const float at = sh_a[t];
        #pragma unroll
        for (int pi = 0; pi < 4; ++pi)
            sY2[IDX(t, i + 16 * pi)] = at * acc2[tj][pi];
    }
    __syncthreads();

    // float4 read-modify-write of y (L2-resident)
    #pragma unroll
    for (int tj = 0; tj < 4; ++tj) {
        const int t = 4 * j + tj;
        const float4 yv2 = *(const float4*)&sY2[IDX(t, 4 * i)];
        float* yrow = y + (((size_t)b * TLEN + t0 + t) * NH + hh) * PP;
        float4 v = *(const float4*)(yrow + 4 * i);
        v.x += yv2.x; v.y += yv2.y; v.z += yv2.z; v.w += yv2.w;
        *(float4*)(yrow + 4 * i) = v;
    }
}

extern "C" void kernel_launch(void* const* d_in, const int* in_sizes, int n_in,
                              void* d_out, int out_size) {
    const float* X     = (const float*)d_in[0];
    const float* delta = (const float*)d_in[1];
    const float* Bm    = (const float*)d_in[2];
    const float* Cm    = (const float*)d_in[3];
    const float* A_log = (const float*)d_in[4];

    float* y     = (float*)d_out;
    float* hlast = y + (size_t)BSZ * TLEN * NH * PP;

    const int kA_smem = 4 * CHL * LDS_ * (int)sizeof(float);  // 69632 B
    const int kC_smem = 2 * CHL * LDS_ * (int)sizeof(float);  // 34816 B
    cudaFuncSetAttribute(kA_intra, cudaFuncAttributeMaxDynamicSharedMemorySize, kA_smem);
    cudaFuncSetAttribute(kC_corr,  cudaFuncAttributeMaxDynamicSharedMemorySize, kC_smem);

    kA_intra<<<BSZ * NH * NCH, 256, kA_smem>>>(X, delta, Bm, Cm, A_log, y);  // 1024 blocks
    k2_scan<<<(BSZ * NH * PP * NN) / 256, 256>>>(hlast);                     // 512 blocks
    kC_corr<<<BSZ * NH * NCH, 256, kC_smem>>>(Cm, y);                        // 1024 blocks
}

// round 12
// speedup vs baseline: 1.1112x; 1.1112x over previous
#include <cuda_runtime.h>

#define BSZ 2
#define TLEN 2048
#define NH 16
#define PP 64
#define NN 64
#define CHL 64                 // chunk length
#define NCH (TLEN / CHL)       // 32 chunks
#define LDS_ (NN + 4)          // padded row stride (68)
#define IDX(r,c) ((r) * LDS_ + (c))

// Scratch (device globals; allocation-free).
__device__ float g_S [BSZ * NH * NCH * PP * NN];  // per-chunk local final state [bh][c][p][n]
__device__ float g_H0[BSZ * NH * NCH * PP * NN];  // state entering each chunk   [bh][c][p][n]
__device__ float g_A [BSZ * NH * NCH];            // per-chunk total decay
__device__ float g_a [BSZ * NH * NCH * CHL];      // a_t = exp(negA*cum_t)

// ---------------------------------------------------------------------------
// KA: fused intra-chunk kernel. One block per (b,h,c), 256 threads.
// 3 smem buffers (sW aliases sC after GEMM1): 52224 B -> 4 blocks/SM.
//   GEMM1 : G[t,s]   = sum_n C[t,n] B[s,n]         (strided 4x4 tile)
//   W^T   : sW[s,t]  = (s<=t) ? exp(negA*(cum_t-cum_s))*delta_s*G : 0
//   GEMM-S: S[p,n]   = sum_s r_s B[s,n] X[s,p]     (consecutive tile, float4)
//   GEMM2 : y[t,p]   = sum_{s<=t} W[t,s] X[s,p]    (consecutive tile, triangular)
// ---------------------------------------------------------------------------
__global__ __launch_bounds__(256) void kA_intra(
    const float* __restrict__ X,      // [B,T,H,P]
    const float* __restrict__ delta,  // [B,T,H]
    const float* __restrict__ Bm,     // [B,T,N]
    const float* __restrict__ Cm,     // [B,T,N]
    const float* __restrict__ A_log,  // [H]
    float* __restrict__ y)            // [B,T,H,P]
{
    extern __shared__ float smem[];
    float* sB = smem;                 // [CHL][LDS_] raw B, later scaled by r_s
    float* sC = sB + CHL * LDS_;      // [CHL][LDS_] C, later W^T (sW aliases it)
    float* sX = sC + CHL * LDS_;      // [CHL][LDS_]
    float* sW = sC;                   // alias: W transposed sW[s][t]

    __shared__ float sh_d[CHL], sh_cum[CHL], sh_r[CHL];
    __shared__ float sh_wsum[2];

    const int blk = blockIdx.x;            // (b*NH+h)*NCH + c
    const int c  = blk % NCH;
    const int hh = (blk / NCH) % NH;
    const int b  = blk / (NCH * NH);
    const int t0 = c * CHL;
    const int tid = threadIdx.x;
    const int lane = tid & 31;

    const float negA = -__expf(A_log[hh]);

    // ---- stage delta + warp-level inclusive scan (phase 1) ----
    if (tid < CHL) {
        const float d = __ldg(delta + ((size_t)b * TLEN + t0 + tid) * NH + hh);
        sh_d[tid] = d;
        float v = d;
        #pragma unroll
        for (int off = 1; off < 32; off <<= 1) {
            const float t = __shfl_up_sync(0xffffffffu, v, off);
            if (lane >= off) v += t;
        }
        sh_cum[tid] = v;
        if (lane == 31) sh_wsum[tid >> 5] = v;
    }

    // ---- stage B, C, X ----
    for (int i = tid; i < CHL * NN / 4; i += 256) {
        const int r = i >> 4, q = i & 15;
        *(float4*)&sB[IDX(r, q * 4)] =
            __ldg((const float4*)(Bm + ((size_t)b * TLEN + t0 + r) * NN) + q);
        *(float4*)&sC[IDX(r, q * 4)] =
            __ldg((const float4*)(Cm + ((size_t)b * TLEN + t0 + r) * NN) + q);
    }
    for (int i = tid; i < CHL * PP / 4; i += 256) {
        const int r = i >> 4, q = i & 15;
        *(float4*)&sX[IDX(r, q * 4)] =
            __ldg((const float4*)(X + (((size_t)b * TLEN + t0 + r) * NH + hh) * PP) + q);
    }
    __syncthreads();   // sync1: staging + scan phase1 done

    // ---- scan phase 2: cross-warp fixup, r_s, a_t, A_c ----
    if (tid < CHL) {
        const float cum = sh_cum[tid] + (tid >= 32 ? sh_wsum[0] : 0.f);
        sh_cum[tid] = cum;
        const float cumTot = sh_wsum[0] + sh_wsum[1];
        g_a[(size_t)blk * CHL + tid] = __expf(negA * cum);
        sh_r[tid] = __expf(negA * (cumTot - cum)) * sh_d[tid];
        if (tid == 0) g_A[blk] = __expf(negA * cumTot);
    }

    const int i = tid & 15;
    const int j = tid >> 4;

    // ---- GEMM1: G[t,s], t = j+16tj, s = i+16si, reduce over n ----
    float g[4][4];
    #pragma unroll
    for (int a0 = 0; a0 < 4; ++a0)
        #pragma unroll
        for (int a1 = 0; a1 < 4; ++a1) g[a0][a1] = 0.f;

    #pragma unroll 4
    for (int n4 = 0; n4 < NN / 4; ++n4) {
        float4 cv[4], bv[4];
        #pragma unroll
        for (int tj = 0; tj < 4; ++tj) cv[tj] = *(const float4*)&sC[IDX(j + 16 * tj, n4 * 4)];
        #pragma unroll
        for (int si = 0; si < 4; ++si) bv[si] = *(const float4*)&sB[IDX(i + 16 * si, n4 * 4)];
        #pragma unroll
        for (int tj = 0; tj < 4; ++tj)
            #pragma unroll
            for (int si = 0; si < 4; ++si) {
                g[tj][si] = fmaf(cv[tj].x, bv[si].x, g[tj][si]);
                g[tj][si] = fmaf(cv[tj].y, bv[si].y, g[tj][si]);
                g[tj][si] = fmaf(cv[tj].z, bv[si].z, g[tj][si]);
                g[tj][si] = fmaf(cv[tj].w, bv[si].w, g[tj][si]);
            }
    }
    __syncthreads();   // sync2: GEMM1 reads of sB/sC done; sh_cum finalized

    // ---- write W transposed into sC's space ----
    #pragma unroll
    for (int tj = 0; tj < 4; ++tj) {
        const int t = j + 16 * tj;
        const float ct = sh_cum[t];
        #pragma unroll
        for (int si = 0; si < 4; ++si) {
            const int s = i + 16 * si;
            const float arg = negA * (ct - sh_cum[s]);
            const float e = __expf(fminf(arg, 0.f));
            sW[IDX(s, t)] = (s <= t) ? e * sh_d[s] * g[tj][si] : 0.f;
        }
    }
    // ---- scale sB in place by r_s ----
    for (int idx = tid; idx < CHL * NN / 4; idx += 256) {
        const int r = idx >> 4, q = idx & 15;
        float4 v = *(float4*)&sB[IDX(r, q * 4)];
        const float rr = sh_r[r];
        v.x *= rr; v.y *= rr; v.z *= rr; v.w *= rr;
        *(float4*)&sB[IDX(r, q * 4)] = v;
    }
    __syncthreads();   // sync3: sW and scaled sB visible

    // ---- GEMM-S: S[p][n] = sum_s sB'[s,n] sX[s,p]; n=4i.., p=4j.. ----
    {
        float acc[4][4];   // [pj][ni]
        #pragma unroll
        for (int a0 = 0; a0 < 4; ++a0)
            #pragma unroll
            for (int a1 = 0; a1 < 4; ++a1) acc[a0][a1] = 0.f;

        #pragma unroll 8
        for (int s = 0; s < CHL; ++s) {
            const float4 bv = *(const float4*)&sB[IDX(s, 4 * i)];
            const float4 xv = *(const float4*)&sX[IDX(s, 4 * j)];
            acc[0][0] = fmaf(xv.x, bv.x, acc[0][0]);
            acc[0][1] = fmaf(xv.x, bv.y, acc[0][1]);
            acc[0][2] = fmaf(xv.x, bv.z, acc[0][2]);
            acc[0][3] = fmaf(xv.x, bv.w, acc[0][3]);
            acc[1][0] = fmaf(xv.y, bv.x, acc[1][0]);
            acc[1][1] = fmaf(xv.y, bv.y, acc[1][1]);
            acc[1][2] = fmaf(xv.y, bv.z, acc[1][2]);
            acc[1][3] = fmaf(xv.y, bv.w, acc[1][3]);
            acc[2][0] = fmaf(xv.z, bv.x, acc[2][0]);
            acc[2][1] = fmaf(xv.z, bv.y, acc[2][1]);
            acc[2][2] = fmaf(xv.z, bv.z, acc[2][2]);
            acc[2][3] = fmaf(xv.z, bv.w, acc[2][3]);
            acc[3][0] = fmaf(xv.w, bv.x, acc[3][0]);
            acc[3][1] = fmaf(xv.w, bv.y, acc[3][1]);
            acc[3][2] = fmaf(xv.w, bv.z, acc[3][2]);
            acc[3][3] = fmaf(xv.w, bv.w, acc[3][3]);
        }
        float* Sp = g_S + (size_t)blk * PP * NN;
        #pragma unroll
        for (int pj = 0; pj < 4; ++pj)
            *(float4*)(Sp + (4 * j + pj) * NN + 4 * i) =
                make_float4(acc[pj][0], acc[pj][1], acc[pj][2], acc[pj][3]);
    }

    // ---- GEMM2: Y1[t,p] = sum_{s<=t} W[t,s] X[s,p]; t=4j.., p=4i.. ----
    {
        const int sBound = ((tid >> 5) + 1) * 8;   // warp-uniform triangular bound
        float acc[4][4];   // [tj][pi]
        #pragma unroll
        for (int a0 = 0; a0 < 4; ++a0)
            #pragma unroll
            for (int a1 = 0; a1 < 4; ++a1) acc[a0][a1] = 0.f;

        #pragma unroll 8
        for (int s = 0; s < sBound; ++s) {
            const float4 wv = *(const float4*)&sW[IDX(s, 4 * j)];
            const float4 xv = *(const float4*)&sX[IDX(s, 4 * i)];
            acc[0][0] = fmaf(wv.x, xv.x, acc[0][0]);
            acc[0][1] = fmaf(wv.x, xv.y, acc[0][1]);
            acc[0][2] = fmaf(wv.x, xv.z, acc[0][2]);
            acc[0][3] = fmaf(wv.x, xv.w, acc[0][3]);
            acc[1][0] = fmaf(wv.y, xv.x, acc[1][0]);
            acc[1][1] = fmaf(wv.y, xv.y, acc[1][1]);
            acc[1][2] = fmaf(wv.y, xv.z, acc[1][2]);
            acc[1][3] = fmaf(wv.y, xv.w, acc[1][3]);
            acc[2][0] = fmaf(wv.z, xv.x, acc[2][0]);
            acc[2][1] = fmaf(wv.z, xv.y, acc[2][1]);
            acc[2][2] = fmaf(wv.z, xv.z, acc[2][2]);
            acc[2][3] = fmaf(wv.z, xv.w, acc[2][3]);
            acc[3][0] = fmaf(wv.w, xv.x, acc[3][0]);
            acc[3][1] = fmaf(wv.w, xv.y, acc[3][1]);
            acc[3][2] = fmaf(wv.w, xv.z, acc[3][2]);
            acc[3][3] = fmaf(wv.w, xv.w, acc[3][3]);
        }
        #pragma unroll
        for (int tj = 0; tj < 4; ++tj) {
            const int t = 4 * j + tj;
            float* yrow = y + (((size_t)b * TLEN + t0 + t) * NH + hh) * PP;
            *(float4*)(yrow + 4 * i) =
                make_float4(acc[tj][0], acc[tj][1], acc[tj][2], acc[tj][3]);
        }
    }
}

// ---------------------------------------------------------------------------
// K2: cross-chunk scan, one thread per (bh, p, n). Fully unrolled over 32 chunks.
// ---------------------------------------------------------------------------
__global__ __launch_bounds__(256) void k2_scan(float* __restrict__ hlast) // [B,H,P,N]
{
    const int idx = blockIdx.x * 256 + threadIdx.x;   // bh*PP*NN + p*NN + n
    const int bh = idx >> 12;
    const int pn = idx & 4095;

    float h = 0.f;
    #pragma unroll
    for (int c = 0; c < NCH; ++c) {
        const size_t off = ((size_t)bh * NCH + c) * (PP * NN) + pn;
        g_H0[off] = h;
        h = fmaf(g_A[bh * NCH + c], h, g_S[off]);
    }
    hlast[(size_t)bh * PP * NN + pn] = h;
}

// ---------------------------------------------------------------------------
// KC: inter-chunk correction. One block per (b,h,c).
//   y[t,p] += a_t * sum_n C[t,n] H0[p,n]
// GEMM3 strided 4x4 tile; result staged via smem for float4 RMW of y.
// ---------------------------------------------------------------------------
__global__ __launch_bounds__(256) void kC_corr(
    const float* __restrict__ Cm,
    float* __restrict__ y)
{
    extern __shared__ float smem[];
    float* sC  = smem;                // [CHL][LDS_]
    float* sH  = sC + CHL * LDS_;     // [PP][LDS_]  -> later sY2[t][p]
    float* sY2 = sH;

    __shared__ float sh_a[CHL];

    const int blk = blockIdx.x;
    const int c  = blk % NCH;
    const int hh = (blk / NCH) % NH;
    const int b  = blk / (NCH * NH);
    const int t0 = c * CHL;
    const int tid = threadIdx.x;

    if (tid < CHL) sh_a[tid] = g_a[(size_t)blk * CHL + tid];
    for (int i = tid; i < CHL * NN / 4; i += 256) {
        const int r = i >> 4, q = i & 15;
        *(float4*)&sC[IDX(r, q * 4)] =
            __ldg((const float4*)(Cm + ((size_t)b * TLEN + t0 + r) * NN) + q);
    }
    {
        const float* Hp = g_H0 + (size_t)blk * PP * NN;
        for (int i = tid; i < PP * NN / 4; i += 256) {
            const int r = i >> 4, q = i & 15;
            *(float4*)&sH[IDX(r, q * 4)] = __ldg((const float4*)Hp + i);
        }
    }
    __syncthreads();

    const int i = tid & 15;
    const int j = tid >> 4;

    // GEMM3: Y2[t,p] = sum_n C[t,n] H0[p,n]; t = j+16tj, p = i+16pi
    float acc2[4][4];
    #pragma unroll
    for (int a0 = 0; a0 < 4; ++a0)
        #pragma unroll
        for (int a1 = 0; a1 < 4; ++a1) acc2[a0][a1] = 0.f;

    #pragma unroll 4
    for (int n4 = 0; n4 < NN / 4; ++n4) {
        float4 cv[4], hv[4];
        #pragma unroll
        for (int tj = 0; tj < 4; ++tj) cv[tj] = *(const float4*)&sC[IDX(j + 16 * tj, n4 * 4)];
        #pragma unroll
        for (int pi = 0; pi < 4; ++pi) hv[pi] = *(const float4*)&sH[IDX(i + 16 * pi, n4 * 4)];
        #pragma unroll
        for (int tj = 0; tj < 4; ++tj)
            #pragma unroll
            for (int pi = 0; pi < 4; ++pi) {
                acc2[tj][pi] = fmaf(cv[tj].x, hv[pi].x, acc2[tj][pi]);
                acc2[tj][pi] = fmaf(cv[tj].y, hv[pi].y, acc2[tj][pi]);
                acc2[tj][pi] = fmaf(cv[tj].z, hv[pi].z, acc2[tj][pi]);
                acc2[tj][pi] = fmaf(cv[tj].w, hv[pi].w, acc2[tj][pi]);
            }
    }
    __syncthreads();   // GEMM3 reads of sH done before sY2 overwrites it

    #pragma unroll
    for (int tj = 0; tj < 4; ++tj) {
        const int t = j + 16 * tj;
        const float at = sh_a[t];
        #pragma unroll
        for (int pi = 0; pi < 4; ++pi)
            sY2[IDX(t, i + 16 * pi)] = at * acc2[tj][pi];
    }
    __syncthreads();

    // float4 read-modify-write of y (L2-resident)
    #pragma unroll
    for (int tj = 0; tj < 4; ++tj) {
        const int t = 4 * j + tj;
        const float4 yv2 = *(const float4*)&sY2[IDX(t, 4 * i)];
        float* yrow = y + (((size_t)b * TLEN + t0 + t) * NH + hh) * PP;
        float4 v = *(const float4*)(yrow + 4 * i);
        v.x += yv2.x; v.y += yv2.y; v.z += yv2.z; v.w += yv2.w;
        *(float4*)(yrow + 4 * i) = v;
    }
}

extern "C" void kernel_launch(void* const* d_in, const int* in_sizes, int n_in,
                              void* d_out, int out_size) {
    const float* X     = (const float*)d_in[0];
    const float* delta = (const float*)d_in[1];
    const float* Bm    = (const float*)d_in[2];
    const float* Cm    = (const float*)d_in[3];
    const float* A_log = (const float*)d_in[4];

    float* y     = (float*)d_out;
    float* hlast = y + (size_t)BSZ * TLEN * NH * PP;

    const int kA_smem = 3 * CHL * LDS_ * (int)sizeof(float);  // 52224 B -> 4 blocks/SM
    const int kC_smem = 2 * CHL * LDS_ * (int)sizeof(float);  // 34816 B
    cudaFuncSetAttribute(kA_intra, cudaFuncAttributeMaxDynamicSharedMemorySize, kA_smem);
    cudaFuncSetAttribute(kC_corr,  cudaFuncAttributeMaxDynamicSharedMemorySize, kC_smem);

    kA_intra<<<BSZ * NH * NCH, 256, kA_smem>>>(X, delta, Bm, Cm, A_log, y);  // 1024 blocks
    k2_scan<<<(BSZ * NH * PP * NN) / 256, 256>>>(hlast);                     // 512 blocks
    kC_corr<<<BSZ * NH * NCH, 256, kC_smem>>>(Cm, y);                        // 1024 blocks
}